// round 3
// baseline (speedup 1.0000x reference)
#include <cuda_runtime.h>

// Fixed problem shapes
#define NS      51                 // hidden size
#define NG      204                // 4*NS
#define T_LEN   2048
#define B_TOT   8192
#define ROWS    64                 // batch rows per block
#define SLICES  8
#define RPS     (ROWS / SLICES)    // 8 rows per thread
#define NPACK   (RPS / 2)          // 4 f32x2 packs
#define HALF_T  (NS * SLICES)      // 408 threads per gate-half
#define NTHREADS (2 * HALF_T)      // 816
#define HP      68                 // float pitch per k-row of h (16B aligned)
#define HSZ     (NS * HP)          // 3468 floats per h buffer
#define WQP     52                 // float4 pitch per k-row of weight quads
#define STG_STR 9                  // ull stride per thread in stage (bank stagger)

typedef unsigned long long ull;

__device__ __forceinline__ ull pack2(float lo, float hi) {
    ull r; asm("mov.b64 %0, {%1, %2};" : "=l"(r) : "f"(lo), "f"(hi)); return r;
}
__device__ __forceinline__ ull fma2(ull a, ull b, ull c) {
    ull d; asm("fma.rn.f32x2 %0, %1, %2, %3;" : "=l"(d) : "l"(a), "l"(b), "l"(c)); return d;
}
__device__ __forceinline__ float2 unpack2(ull v) {
    float lo, hi; asm("mov.b64 {%0, %1}, %2;" : "=f"(lo), "=f"(hi) : "l"(v));
    return make_float2(lo, hi);
}
__device__ __forceinline__ float sigm(float v) {
    return 1.0f / (1.0f + __expf(-v));
}
__device__ __forceinline__ float tanh_fast(float v) {
    return 2.0f / (1.0f + __expf(-2.0f * v)) - 1.0f;
}

// Full LSTM pointwise for one 2-row pack: Ai,Af,Ag,Ao are packed preacts.
__device__ __forceinline__ void lstm_act2(ull Ai, ull Af, ull Ag, ull Ao,
                                          float* c, float* hn) {
    float2 ai = unpack2(Ai), af = unpack2(Af), ag = unpack2(Ag), ao = unpack2(Ao);
    float cx = fmaf(sigm(af.x), c[0], sigm(ai.x) * tanh_fast(ag.x));
    c[0] = cx;  hn[0] = sigm(ao.x) * tanh_fast(cx);
    float cy = fmaf(sigm(af.y), c[1], sigm(ai.y) * tanh_fast(ag.y));
    c[1] = cy;  hn[1] = sigm(ao.y) * tanh_fast(cy);
}

__global__ __launch_bounds__(NTHREADS, 1)
void lstm2_gsplit_kernel(
    const float* __restrict__ x,      // [B, T]
    const float* __restrict__ Wih1,   // [204, 1]
    const float* __restrict__ Whh1,   // [204, 51]
    const float* __restrict__ bih1,
    const float* __restrict__ bhh1,
    const float* __restrict__ Wih2,   // [204, 51]
    const float* __restrict__ Whh2,   // [204, 51]
    const float* __restrict__ bih2,
    const float* __restrict__ bhh2,
    const float* __restrict__ Wlin,   // [1, 51]
    const float* __restrict__ blin,
    float* __restrict__ out)          // [B, T]
{
    extern __shared__ ull smu[];
    ull*    stg  = smu;                               // [HALF_T][STG_STR] preact stage
    float*  smf  = (float*)(smu + HALF_T * STG_STR);
    float4* wq1  = (float4*)smf;                      // [NS][WQP] gate quads of Whh1
    float4* wqi2 = wq1  + NS * WQP;
    float4* wqh2 = wqi2 + NS * WQP;
    float*  h1   = (float*)(wqh2 + NS * WQP);         // [2][NS][HP]
    float*  h2   = h1 + 2 * HSZ;
    float*  b1s  = h2 + 2 * HSZ;                      // [NG] combined biases
    float*  b2s  = b1s + NG;
    float*  wi1s = b2s + NG;                          // [NG]
    float*  wls  = wi1s + NG;                         // [52]
    float*  xs   = wls + 52;                          // [2][64] double-buffered x

    const int tid = threadIdx.x;
    const int rb  = blockIdx.x * ROWS;

    // ---- init: transpose weights into gate quads, combine biases, zero states ----
    for (int i = tid; i < NG * NS; i += NTHREADS) {
        int g = i / NS, k = i % NS;
        int jj = g % NS, gi = g / NS;
        ((float*)&wq1 [k * WQP + jj])[gi] = Whh1[i];
        ((float*)&wqi2[k * WQP + jj])[gi] = Wih2[i];
        ((float*)&wqh2[k * WQP + jj])[gi] = Whh2[i];
    }
    for (int i = tid; i < NG; i += NTHREADS) {
        b1s[i]  = bih1[i] + bhh1[i];
        b2s[i]  = bih2[i] + bhh2[i];
        wi1s[i] = Wih1[i];
    }
    for (int i = tid; i < NS; i += NTHREADS) wls[i] = Wlin[i];
    for (int i = tid; i < 2 * HSZ; i += NTHREADS) { h1[i] = 0.0f; h2[i] = 0.0f; }
    if (tid < ROWS) xs[tid] = x[(size_t)(rb + tid) * T_LEN];
    const float blin_v = blin[0];
    __syncthreads();

    const int gp = tid / HALF_T;        // 0: gates (i,f), 1: gates (g,o)
    const int r  = tid % HALF_T;
    const int j  = r % NS;              // hidden unit 0..50
    const int sl = r / NS;              // row slice 0..7
    const int r0 = sl * RPS;
    const int g0 = 2 * gp, g1 = 2 * gp + 1;

    // per-thread packed constants for own two gates
    const ull wx0  = pack2(wi1s[j + g0 * NS], wi1s[j + g0 * NS]);
    const ull wx1  = pack2(wi1s[j + g1 * NS], wi1s[j + g1 * NS]);
    const ull b1d0 = pack2(b1s[j + g0 * NS], b1s[j + g0 * NS]);
    const ull b1d1 = pack2(b1s[j + g1 * NS], b1s[j + g1 * NS]);
    const ull b2d0 = pack2(b2s[j + g0 * NS], b2s[j + g0 * NS]);
    const ull b2d1 = pack2(b2s[j + g1 * NS], b2s[j + g1 * NS]);

    ull* myStg = stg + (size_t)(sl * NS + j) * STG_STR;

    float c1[RPS], c2[RPS];             // c1 used by gp1 threads, c2 by gp0
    #pragma unroll
    for (int i = 0; i < RPS; ++i) { c1[i] = 0.0f; c2[i] = 0.0f; }

    int bf = 0;
    for (int t = 0; t < T_LEN; ++t) {
        const int nb = bf ^ 1;
        const float* h1o = h1 + bf * HSZ;
        float*       h1n = h1 + nb * HSZ;
        const float* h2o = h2 + bf * HSZ;
        float*       h2n = h2 + nb * HSZ;
        const float* xcur = xs + (t & 1) * 64;

        ull a0[NPACK], a1[NPACK];

        // ---------- Phase 1: layer-1 preacts for own 2 gates ----------
        {
            ulonglong2 xA = *(const ulonglong2*)(xcur + r0);
            ulonglong2 xB = *(const ulonglong2*)(xcur + r0 + 4);
            ull xp[NPACK] = {xA.x, xA.y, xB.x, xB.y};
            #pragma unroll
            for (int p = 0; p < NPACK; ++p) {
                a0[p] = fma2(xp[p], wx0, b1d0);
                a1[p] = fma2(xp[p], wx1, b1d1);
            }
            #pragma unroll 3
            for (int k = 0; k < NS; ++k) {
                float2 w = *(const float2*)((const char*)&wq1[k * WQP + j] + gp * 8);
                ull w0 = pack2(w.x, w.x), w1 = pack2(w.y, w.y);
                const float* hp = h1o + k * HP + r0;
                ulonglong2 hA = *(const ulonglong2*)hp;
                ulonglong2 hB = *(const ulonglong2*)(hp + 4);
                ull hv[NPACK] = {hA.x, hA.y, hB.x, hB.y};
                #pragma unroll
                for (int p = 0; p < NPACK; ++p) {
                    a0[p] = fma2(hv[p], w0, a0[p]);
                    a1[p] = fma2(hv[p], w1, a1[p]);
                }
            }
        }
        if (gp == 0) {   // hand (i,f) preacts to partner
            #pragma unroll
            for (int p = 0; p < NPACK; ++p) { myStg[p] = a0[p]; myStg[NPACK + p] = a1[p]; }
        }
        __syncthreads();

        // ---------- Phase 2: gp1 does layer-1 pointwise; gp0 does proj(t-1)+prefetch ----------
        if (gp == 1) {
            float hn[RPS];
            #pragma unroll
            for (int p = 0; p < NPACK; ++p)
                lstm_act2(myStg[p], myStg[NPACK + p], a0[p], a1[p],
                          c1 + 2 * p, hn + 2 * p);
            float* dst = h1n + j * HP + r0;
            *(float4*)dst       = make_float4(hn[0], hn[1], hn[2], hn[3]);
            *(float4*)(dst + 4) = make_float4(hn[4], hn[5], hn[6], hn[7]);
        } else if (r < ROWS) {
            if (t > 0) {     // projection of previous step's h2 (stable buffer h2o)
                float acc = blin_v;
                #pragma unroll
                for (int k = 0; k < NS; ++k)
                    acc = fmaf(h2o[k * HP + r], wls[k], acc);
                out[(size_t)(rb + r) * T_LEN + (t - 1)] = acc;
            }
        } else if (r < 2 * ROWS) {
            int rr = r - ROWS;
            if (t + 1 < T_LEN)
                xs[((t + 1) & 1) * 64 + rr] = x[(size_t)(rb + rr) * T_LEN + (t + 1)];
        }
        __syncthreads();

        // ---------- Phase 3: layer-2 preacts for own 2 gates (K = h1n ++ h2o) ----------
        {
            #pragma unroll
            for (int p = 0; p < NPACK; ++p) { a0[p] = b2d0; a1[p] = b2d1; }
            #pragma unroll 3
            for (int k = 0; k < NS; ++k) {
                float2 wi = *(const float2*)((const char*)&wqi2[k * WQP + j] + gp * 8);
                float2 wh = *(const float2*)((const char*)&wqh2[k * WQP + j] + gp * 8);
                ull wi0 = pack2(wi.x, wi.x), wi1d = pack2(wi.y, wi.y);
                ull wh0 = pack2(wh.x, wh.x), wh1d = pack2(wh.y, wh.y);
                const float* p1 = h1n + k * HP + r0;
                const float* p2 = h2o + k * HP + r0;
                ulonglong2 h1A = *(const ulonglong2*)p1;
                ulonglong2 h1B = *(const ulonglong2*)(p1 + 4);
                ulonglong2 h2A = *(const ulonglong2*)p2;
                ulonglong2 h2B = *(const ulonglong2*)(p2 + 4);
                ull hv1[NPACK] = {h1A.x, h1A.y, h1B.x, h1B.y};
                ull hv2[NPACK] = {h2A.x, h2A.y, h2B.x, h2B.y};
                #pragma unroll
                for (int p = 0; p < NPACK; ++p) {
                    a0[p] = fma2(hv1[p], wi0,  a0[p]);
                    a1[p] = fma2(hv1[p], wi1d, a1[p]);
                    a0[p] = fma2(hv2[p], wh0,  a0[p]);
                    a1[p] = fma2(hv2[p], wh1d, a1[p]);
                }
            }
        }
        if (gp == 1) {   // hand (g,o) preacts to partner
            #pragma unroll
            for (int p = 0; p < NPACK; ++p) { myStg[p] = a0[p]; myStg[NPACK + p] = a1[p]; }
        }
        __syncthreads();

        // ---------- Phase 4: gp0 does layer-2 pointwise, writes h2n ----------
        if (gp == 0) {
            float hn[RPS];
            #pragma unroll
            for (int p = 0; p < NPACK; ++p)
                lstm_act2(a0[p], a1[p], myStg[p], myStg[NPACK + p],
                          c2 + 2 * p, hn + 2 * p);
            float* dst = h2n + j * HP + r0;
            *(float4*)dst       = make_float4(hn[0], hn[1], hn[2], hn[3]);
            *(float4*)(dst + 4) = make_float4(hn[4], hn[5], hn[6], hn[7]);
        }
        __syncthreads();
        bf = nb;
    }

    // ---------- final projection for t = T_LEN-1 (h2n is in buffer bf) ----------
    if (gp == 0 && r < ROWS) {
        const float* h2f = h2 + bf * HSZ;
        float acc = blin_v;
        #pragma unroll
        for (int k = 0; k < NS; ++k)
            acc = fmaf(h2f[k * HP + r], wls[k], acc);
        out[(size_t)(rb + r) * T_LEN + (T_LEN - 1)] = acc;
    }
}

extern "C" void kernel_launch(void* const* d_in, const int* in_sizes, int n_in,
                              void* d_out, int out_size) {
    const float* x    = (const float*)d_in[0];
    const float* Wih1 = (const float*)d_in[1];
    const float* Whh1 = (const float*)d_in[2];
    const float* bih1 = (const float*)d_in[3];
    const float* bhh1 = (const float*)d_in[4];
    const float* Wih2 = (const float*)d_in[5];
    const float* Whh2 = (const float*)d_in[6];
    const float* bih2 = (const float*)d_in[7];
    const float* bhh2 = (const float*)d_in[8];
    const float* Wlin = (const float*)d_in[9];
    const float* blin = (const float*)d_in[10];
    float* out = (float*)d_out;

    size_t smem = (size_t)HALF_T * STG_STR * sizeof(ull)                 // stage
                + (size_t)(3 * NS * WQP * 4) * sizeof(float)             // weight quads
                + (size_t)(4 * HSZ) * sizeof(float)                      // h buffers
                + (size_t)(3 * NG + 52 + 128) * sizeof(float);           // biases, wlin, xs
    cudaFuncSetAttribute(lstm2_gsplit_kernel,
                         cudaFuncAttributeMaxDynamicSharedMemorySize, (int)smem);

    dim3 grid(B_TOT / ROWS);      // 128 blocks
    dim3 block(NTHREADS);         // 816 threads
    lstm2_gsplit_kernel<<<grid, block, smem>>>(
        x, Wih1, Whh1, bih1, bhh1, Wih2, Whh2, bih2, bhh2, Wlin, blin, out);
}

// round 4
// speedup vs baseline: 1.2941x; 1.2941x over previous
#include <cuda_runtime.h>

// Fixed problem shapes
#define NS      51                 // hidden size
#define NG      204                // 4*NS
#define T_LEN   2048
#define B_TOT   8192
#define ROWS    64                 // batch rows per block
#define SLICES  8
#define RPS     (ROWS / SLICES)    // 8 rows per thread
#define NPACK   (RPS / 2)          // 4 f32x2 packs
#define GWORK   (NS * SLICES)      // 408 gate-worker threads
#define NTHREADS 512               // 408 workers + helpers (448..511)
#define HELP0   448
#define HP      68                 // float pitch per k-row of h
#define HSZ     (NS * HP)
#define WQP     52                 // float4 pitch per k-row of weight quads

typedef unsigned long long ull;

__device__ __forceinline__ ull pack2(float lo, float hi) {
    ull r; asm("mov.b64 %0, {%1, %2};" : "=l"(r) : "f"(lo), "f"(hi)); return r;
}
__device__ __forceinline__ ull fma2(ull a, ull b, ull c) {
    ull d; asm("fma.rn.f32x2 %0, %1, %2, %3;" : "=l"(d) : "l"(a), "l"(b), "l"(c)); return d;
}
__device__ __forceinline__ float2 unpack2(ull v) {
    float lo, hi; asm("mov.b64 {%0, %1}, %2;" : "=f"(lo), "=f"(hi) : "l"(v));
    return make_float2(lo, hi);
}
__device__ __forceinline__ float sigm(float v) {
    return 1.0f / (1.0f + __expf(-v));
}
__device__ __forceinline__ float tanh_fast(float v) {
    return 2.0f / (1.0f + __expf(-2.0f * v)) - 1.0f;
}

__device__ __forceinline__ void lstm_act2(ull Ai, ull Af, ull Ag, ull Ao,
                                          float* c, float* hn) {
    float2 ai = unpack2(Ai), af = unpack2(Af), ag = unpack2(Ag), ao = unpack2(Ao);
    float cx = fmaf(sigm(af.x), c[0], sigm(ai.x) * tanh_fast(ag.x));
    c[0] = cx;  hn[0] = sigm(ao.x) * tanh_fast(cx);
    float cy = fmaf(sigm(af.y), c[1], sigm(ai.y) * tanh_fast(ag.y));
    c[1] = cy;  hn[1] = sigm(ao.y) * tanh_fast(cy);
}

__global__ __launch_bounds__(NTHREADS, 1)
void lstm2_v4_kernel(
    const float* __restrict__ x,      // [B, T]
    const float* __restrict__ Wih1,   // [204, 1]
    const float* __restrict__ Whh1,   // [204, 51]
    const float* __restrict__ bih1,
    const float* __restrict__ bhh1,
    const float* __restrict__ Wih2,   // [204, 51]
    const float* __restrict__ Whh2,   // [204, 51]
    const float* __restrict__ bih2,
    const float* __restrict__ bhh2,
    const float* __restrict__ Wlin,   // [1, 51]
    const float* __restrict__ blin,
    float* __restrict__ out)          // [B, T]
{
    extern __shared__ float sm[];
    float4* wq1  = (float4*)sm;                       // [NS][WQP] gate quads of Whh1
    float4* wqi2 = wq1  + NS * WQP;
    float4* wqh2 = wqi2 + NS * WQP;
    float*  h1   = (float*)(wqh2 + NS * WQP);         // [2][NS][HP]
    float*  h2   = h1 + 2 * HSZ;
    float*  b1s  = h2 + 2 * HSZ;                      // [NG]
    float*  b2s  = b1s + NG;
    float*  wi1s = b2s + NG;                          // [NG]
    float*  wls  = wi1s + NG;                         // [52]
    float*  xs   = wls + 52;                          // [2][64]

    const int tid = threadIdx.x;
    const int rb  = blockIdx.x * ROWS;

    // ---- init ----
    for (int i = tid; i < NG * NS; i += NTHREADS) {
        int g = i / NS, k = i % NS;
        int jj = g % NS, gi = g / NS;
        ((float*)&wq1 [k * WQP + jj])[gi] = Whh1[i];
        ((float*)&wqi2[k * WQP + jj])[gi] = Wih2[i];
        ((float*)&wqh2[k * WQP + jj])[gi] = Whh2[i];
    }
    for (int i = tid; i < NG; i += NTHREADS) {
        b1s[i]  = bih1[i] + bhh1[i];
        b2s[i]  = bih2[i] + bhh2[i];
        wi1s[i] = Wih1[i];
    }
    for (int i = tid; i < NS; i += NTHREADS) wls[i] = Wlin[i];
    for (int i = tid; i < 2 * HSZ; i += NTHREADS) { h1[i] = 0.0f; h2[i] = 0.0f; }
    if (tid < ROWS) xs[tid] = x[(size_t)(rb + tid) * T_LEN];
    const float blin_v = blin[0];
    __syncthreads();

    const bool worker = (tid < GWORK);
    const bool helper = (tid >= HELP0);
    const int  j  = tid % NS;
    const int  sl = (tid / NS) & 7;
    const int  r0 = sl * RPS;
    const int  hrow = tid - HELP0;       // helper's batch row 0..63

    // per-thread packed constants (workers only use them)
    ull wxd[4], b1d[4], b2d[4];
    #pragma unroll
    for (int gi = 0; gi < 4; ++gi) {
        float wv  = wi1s[j + gi * NS];
        float bv1 = b1s[j + gi * NS];
        float bv2 = b2s[j + gi * NS];
        wxd[gi] = pack2(wv, wv);
        b1d[gi] = pack2(bv1, bv1);
        b2d[gi] = pack2(bv2, bv2);
    }

    float c1[RPS], c2[RPS];
    #pragma unroll
    for (int i = 0; i < RPS; ++i) { c1[i] = 0.0f; c2[i] = 0.0f; }

    int bf = 0;
    for (int t = 0; t < T_LEN; ++t) {
        const int nb = bf ^ 1;
        const float* h1o = h1 + bf * HSZ;
        float*       h1n = h1 + nb * HSZ;
        const float* h2o = h2 + bf * HSZ;   // also holds h2 result of step t-1
        float*       h2n = h2 + nb * HSZ;
        const float* xcur = xs + (t & 1) * 64;

        // ===== Phase A: workers do layer-1; helpers do proj(t-1) + prefetch =====
        if (worker) {
            ull a0[NPACK], a1[NPACK], a2[NPACK], a3[NPACK];
            ulonglong2 xA = *(const ulonglong2*)(xcur + r0);
            ulonglong2 xB = *(const ulonglong2*)(xcur + r0 + 4);
            ull xp[NPACK] = {xA.x, xA.y, xB.x, xB.y};
            #pragma unroll
            for (int p = 0; p < NPACK; ++p) {
                a0[p] = fma2(xp[p], wxd[0], b1d[0]);
                a1[p] = fma2(xp[p], wxd[1], b1d[1]);
                a2[p] = fma2(xp[p], wxd[2], b1d[2]);
                a3[p] = fma2(xp[p], wxd[3], b1d[3]);
            }
            #pragma unroll 4
            for (int k = 0; k < NS; ++k) {
                float4 w = wq1[k * WQP + j];
                ull w0 = pack2(w.x, w.x), w1 = pack2(w.y, w.y);
                ull w2 = pack2(w.z, w.z), w3 = pack2(w.w, w.w);
                const float* hp = h1o + k * HP + r0;
                ulonglong2 hA = *(const ulonglong2*)hp;
                ulonglong2 hB = *(const ulonglong2*)(hp + 4);
                ull hv[NPACK] = {hA.x, hA.y, hB.x, hB.y};
                #pragma unroll
                for (int p = 0; p < NPACK; ++p) {
                    a0[p] = fma2(hv[p], w0, a0[p]);
                    a1[p] = fma2(hv[p], w1, a1[p]);
                    a2[p] = fma2(hv[p], w2, a2[p]);
                    a3[p] = fma2(hv[p], w3, a3[p]);
                }
            }
            float hn[RPS];
            #pragma unroll
            for (int p = 0; p < NPACK; ++p)
                lstm_act2(a0[p], a1[p], a2[p], a3[p], c1 + 2 * p, hn + 2 * p);
            float* dst = h1n + j * HP + r0;
            *(float4*)dst       = make_float4(hn[0], hn[1], hn[2], hn[3]);
            *(float4*)(dst + 4) = make_float4(hn[4], hn[5], hn[6], hn[7]);
        } else if (helper) {
            if (t + 1 < T_LEN)
                xs[((t + 1) & 1) * 64 + hrow] =
                    x[(size_t)(rb + hrow) * T_LEN + (t + 1)];
            if (t > 0) {   // projection of h2 from step t-1 (lives in h2o buffer)
                float acc = blin_v;
                #pragma unroll 4
                for (int k = 0; k < NS; ++k)
                    acc = fmaf(h2o[k * HP + hrow], wls[k], acc);
                out[(size_t)(rb + hrow) * T_LEN + (t - 1)] = acc;
            }
        }
        __syncthreads();   // h1n + next-x visible

        // ===== Phase C: workers do layer-2 (K over h1n and h2o) =====
        if (worker) {
            ull a0[NPACK], a1[NPACK], a2[NPACK], a3[NPACK];
            #pragma unroll
            for (int p = 0; p < NPACK; ++p) {
                a0[p] = b2d[0]; a1[p] = b2d[1]; a2[p] = b2d[2]; a3[p] = b2d[3];
            }
            #pragma unroll 4
            for (int k = 0; k < NS; ++k) {
                float4 wi = wqi2[k * WQP + j];
                float4 wh = wqh2[k * WQP + j];
                ull wi0 = pack2(wi.x, wi.x), wi1d = pack2(wi.y, wi.y);
                ull wi2d = pack2(wi.z, wi.z), wi3 = pack2(wi.w, wi.w);
                ull wh0 = pack2(wh.x, wh.x), wh1d = pack2(wh.y, wh.y);
                ull wh2d = pack2(wh.z, wh.z), wh3 = pack2(wh.w, wh.w);
                const float* p1 = h1n + k * HP + r0;
                const float* p2 = h2o + k * HP + r0;
                ulonglong2 h1A = *(const ulonglong2*)p1;
                ulonglong2 h1B = *(const ulonglong2*)(p1 + 4);
                ulonglong2 h2A = *(const ulonglong2*)p2;
                ulonglong2 h2B = *(const ulonglong2*)(p2 + 4);
                ull hv1[NPACK] = {h1A.x, h1A.y, h1B.x, h1B.y};
                ull hv2[NPACK] = {h2A.x, h2A.y, h2B.x, h2B.y};
                #pragma unroll
                for (int p = 0; p < NPACK; ++p) {
                    a0[p] = fma2(hv1[p], wi0,  a0[p]);
                    a1[p] = fma2(hv1[p], wi1d, a1[p]);
                    a2[p] = fma2(hv1[p], wi2d, a2[p]);
                    a3[p] = fma2(hv1[p], wi3,  a3[p]);
                    a0[p] = fma2(hv2[p], wh0,  a0[p]);
                    a1[p] = fma2(hv2[p], wh1d, a1[p]);
                    a2[p] = fma2(hv2[p], wh2d, a2[p]);
                    a3[p] = fma2(hv2[p], wh3,  a3[p]);
                }
            }
            float hn[RPS];
            #pragma unroll
            for (int p = 0; p < NPACK; ++p)
                lstm_act2(a0[p], a1[p], a2[p], a3[p], c2 + 2 * p, hn + 2 * p);
            float* dst = h2n + j * HP + r0;
            *(float4*)dst       = make_float4(hn[0], hn[1], hn[2], hn[3]);
            *(float4*)(dst + 4) = make_float4(hn[4], hn[5], hn[6], hn[7]);
        }
        __syncthreads();   // h2n visible
        bf = nb;
    }

    // ---- final projection for t = T_LEN-1 (h2 result sits in buffer bf) ----
    if (helper) {
        const float* h2f = h2 + bf * HSZ;
        float acc = blin_v;
        #pragma unroll 4
        for (int k = 0; k < NS; ++k)
            acc = fmaf(h2f[k * HP + hrow], wls[k], acc);
        out[(size_t)(rb + hrow) * T_LEN + (T_LEN - 1)] = acc;
    }
}

extern "C" void kernel_launch(void* const* d_in, const int* in_sizes, int n_in,
                              void* d_out, int out_size) {
    const float* x    = (const float*)d_in[0];
    const float* Wih1 = (const float*)d_in[1];
    const float* Whh1 = (const float*)d_in[2];
    const float* bih1 = (const float*)d_in[3];
    const float* bhh1 = (const float*)d_in[4];
    const float* Wih2 = (const float*)d_in[5];
    const float* Whh2 = (const float*)d_in[6];
    const float* bih2 = (const float*)d_in[7];
    const float* bhh2 = (const float*)d_in[8];
    const float* Wlin = (const float*)d_in[9];
    const float* blin = (const float*)d_in[10];
    float* out = (float*)d_out;

    size_t smem = (size_t)(3 * NS * WQP * 4 + 4 * HSZ + 3 * NG + 52 + 128)
                  * sizeof(float);
    cudaFuncSetAttribute(lstm2_v4_kernel,
                         cudaFuncAttributeMaxDynamicSharedMemorySize, (int)smem);

    dim3 grid(B_TOT / ROWS);      // 128 blocks
    dim3 block(NTHREADS);         // 512 threads (408 workers + helpers)
    lstm2_v4_kernel<<<grid, block, smem>>>(
        x, Wih1, Whh1, bih1, bhh1, Wih2, Whh2, bih2, bhh2, Wlin, blin, out);
}